// round 1
// baseline (speedup 1.0000x reference)
#include <cuda_runtime.h>
#include <cuda_bf16.h>
#include <cstdint>

// Problem constants (fixed shapes)
#define MTOK   24000      // B*T = 16*1500
#define FD     1280       // d_model
#define LAY    32         // layers
#define NE     8          // experts
#define N1     256        // LAY*NE
#define LN_EPS 1e-5f

// ---------------------------------------------------------------------------
// Scratch (static __device__ arrays -- allocation-free per harness rules)
// ---------------------------------------------------------------------------
__device__ __nv_bfloat16 g_xb[(size_t)MTOK * FD];        // x in bf16        61.4 MB
__device__ __nv_bfloat16 g_Wt[N1 * FD];                  // router_w as [n][f] bf16
__device__ __nv_bfloat16 g_svT[FD * N1];                 // steering as [f][n] bf16
__device__ float         g_Ms[LAY * LAY * NE * NE];      // s_j * sv_j @ Wr_l  [j][l][a][b]
__device__ float         g_base[(size_t)MTOK * N1];      // x @ Wr            24.6 MB
__device__ __nv_bfloat16 g_gates[(size_t)MTOK * N1];     // s_j*gate_j bf16   12.3 MB
__device__ float         g_h[(size_t)MTOK * FD];         // x + adj          123 MB

// ---------------------------------------------------------------------------
// small asm helpers
// ---------------------------------------------------------------------------
__device__ __forceinline__ uint32_t smem_u32(const void* p) {
    return (uint32_t)__cvta_generic_to_shared(p);
}
__device__ __forceinline__ void cp_async16(void* smem, const void* gmem, int sz) {
    asm volatile("cp.async.cg.shared.global [%0], [%1], 16, %2;\n"
                 :: "r"(smem_u32(smem)), "l"(gmem), "r"(sz));
}
__device__ __forceinline__ void cp_commit() {
    asm volatile("cp.async.commit_group;\n" ::);
}
__device__ __forceinline__ void cp_wait1() {
    asm volatile("cp.async.wait_group 1;\n" ::);
}
__device__ __forceinline__ void ldsm_x4(uint32_t* r, uint32_t a) {
    asm volatile("ldmatrix.sync.aligned.m8n8.x4.shared.b16 {%0,%1,%2,%3}, [%4];\n"
                 : "=r"(r[0]), "=r"(r[1]), "=r"(r[2]), "=r"(r[3]) : "r"(a));
}
__device__ __forceinline__ void ldsm_x2(uint32_t* r, uint32_t a) {
    asm volatile("ldmatrix.sync.aligned.m8n8.x2.shared.b16 {%0,%1}, [%2];\n"
                 : "=r"(r[0]), "=r"(r[1]) : "r"(a));
}
__device__ __forceinline__ void mma_bf16(float* c, const uint32_t* a, const uint32_t* b) {
    asm volatile("mma.sync.aligned.m16n8k16.row.col.f32.bf16.bf16.f32 "
                 "{%0,%1,%2,%3}, {%4,%5,%6,%7}, {%8,%9}, {%0,%1,%2,%3};\n"
                 : "+f"(c[0]), "+f"(c[1]), "+f"(c[2]), "+f"(c[3])
                 : "r"(a[0]), "r"(a[1]), "r"(a[2]), "r"(a[3]), "r"(b[0]), "r"(b[1]));
}

// ---------------------------------------------------------------------------
// Prep kernels
// ---------------------------------------------------------------------------
__global__ __launch_bounds__(256) void convert_x_kernel(const float* __restrict__ x) {
    int i = blockIdx.x * 256 + threadIdx.x;           // 7,680,000 float4s exactly
    float4 v = ((const float4*)x)[i];
    __nv_bfloat162* o = (__nv_bfloat162*)g_xb;
    o[2 * i]     = __floats2bfloat162_rn(v.x, v.y);
    o[2 * i + 1] = __floats2bfloat162_rn(v.z, v.w);
}

__global__ __launch_bounds__(256) void prep_w_kernel(const float* __restrict__ wr,
                                                     const float* __restrict__ sv) {
    int idx = blockIdx.x * 256 + threadIdx.x;         // 327,680 exactly
    int n = idx / FD, f = idx % FD;
    int l = n >> 3, e = n & 7;
    g_Wt[idx]           = __float2bfloat16(wr[((size_t)l * FD + f) * NE + e]);
    g_svT[(size_t)f * N1 + n] = __float2bfloat16(sv[(size_t)n * FD + f]);
}

// Ms[j][l][a][b] = s_j * sum_f sv[j,a,f] * wr[l,f,b]
__global__ __launch_bounds__(64) void prep_ms_kernel(const float* __restrict__ sv,
                                                     const float* __restrict__ wr,
                                                     const float* __restrict__ ls) {
    int j = blockIdx.x, l = blockIdx.y;
    int b = threadIdx.x & 7, a = threadIdx.x >> 3;
    const float* svp = sv + (size_t)(j * NE + a) * FD;
    const float* wrp = wr + (size_t)l * FD * NE + b;
    float s = 0.f;
    #pragma unroll 4
    for (int f = 0; f < FD; f++) s = fmaf(svp[f], wrp[f * NE], s);
    g_Ms[((j * LAY + l) * NE + a) * NE + b] = s * ls[j];
}

// ---------------------------------------------------------------------------
// bf16 tensor-core GEMM:  C[M,N] = A[M,K] * B[N,K]^T   (mma.sync m16n8k16)
// PHASE 1: base = x_bf16 @ Wt^T    (N=256, K=1280)
// PHASE 2: h    = x + gates @ svT^T (N=1280, K=256, epilogue adds x)
// ---------------------------------------------------------------------------
#define GBM 128
#define GBN 64
#define GBK 32
#define GPAD 8

template<int PHASE>
__global__ __launch_bounds__(256) void gemm_k(const float* __restrict__ Xepi) {
    constexpr int N = (PHASE == 1) ? N1 : FD;
    constexpr int K = (PHASE == 1) ? FD : N1;
    constexpr bool EPI = (PHASE == 2);
    const __nv_bfloat16* __restrict__ A  = (PHASE == 1) ? g_xb : g_gates;
    const __nv_bfloat16* __restrict__ Bm = (PHASE == 1) ? g_Wt : g_svT;
    float* __restrict__ C = (PHASE == 1) ? g_base : g_h;

    __shared__ __nv_bfloat16 As[2][GBM][GBK + GPAD];
    __shared__ __nv_bfloat16 Bs[2][GBN][GBK + GPAD];

    const int tid = threadIdx.x, lane = tid & 31, wrp = tid >> 5;
    const int wm = wrp & 3, wn = wrp >> 2;           // 4 x 2 warp grid
    const int m0 = blockIdx.y * GBM, n0 = blockIdx.x * GBN;
    const int ar = tid >> 2, ac = (tid & 3) * 8;

    float acc[2][4][4];
    #pragma unroll
    for (int mt = 0; mt < 2; mt++)
        #pragma unroll
        for (int nt = 0; nt < 4; nt++)
            #pragma unroll
            for (int q = 0; q < 4; q++) acc[mt][nt][q] = 0.f;

    auto load_tiles = [&](int buf, int kt) {
        const int k0 = kt * GBK + ac;
        #pragma unroll
        for (int p = 0; p < 2; p++) {
            int m = m0 + ar + p * 64;
            const __nv_bfloat16* src = A + (size_t)((m < MTOK) ? m : 0) * K + k0;
            cp_async16(&As[buf][ar + p * 64][ac], src, (m < MTOK) ? 16 : 0);
        }
        cp_async16(&Bs[buf][ar][ac], Bm + (size_t)(n0 + ar) * K + k0, 16);
    };

    load_tiles(0, 0);
    cp_commit();
    constexpr int KT = K / GBK;
    for (int kt = 0; kt < KT; kt++) {
        if (kt + 1 < KT) load_tiles((kt + 1) & 1, kt + 1);
        cp_commit();
        cp_wait1();
        __syncthreads();
        const int buf = kt & 1;
        #pragma unroll
        for (int ks = 0; ks < 2; ks++) {
            uint32_t af[2][4], bfr[4][2];
            #pragma unroll
            for (int mt = 0; mt < 2; mt++) {
                uint32_t addr = smem_u32(&As[buf][wm * 32 + mt * 16 + (lane & 15)]
                                            [ks * 16 + (lane >> 4) * 8]);
                ldsm_x4(af[mt], addr);
            }
            #pragma unroll
            for (int nt = 0; nt < 4; nt++) {
                uint32_t addr = smem_u32(&Bs[buf][wn * 32 + nt * 8 + (lane & 7)]
                                            [ks * 16 + ((lane >> 3) & 1) * 8]);
                ldsm_x2(bfr[nt], addr);
            }
            #pragma unroll
            for (int mt = 0; mt < 2; mt++)
                #pragma unroll
                for (int nt = 0; nt < 4; nt++)
                    mma_bf16(acc[mt][nt], af[mt], bfr[nt]);
        }
        __syncthreads();
    }

    const int gid = lane >> 2, qid = lane & 3;
    #pragma unroll
    for (int mt = 0; mt < 2; mt++) {
        #pragma unroll
        for (int nt = 0; nt < 4; nt++) {
            int n = n0 + wn * 32 + nt * 8 + qid * 2;
            #pragma unroll
            for (int h = 0; h < 2; h++) {
                int m = m0 + wm * 32 + mt * 16 + gid + h * 8;
                if (m < MTOK) {
                    float2 v = make_float2(acc[mt][nt][h * 2], acc[mt][nt][h * 2 + 1]);
                    if (EPI) {
                        float2 xv = *(const float2*)&Xepi[(size_t)m * N + n];
                        v.x += xv.x; v.y += xv.y;
                    }
                    *(float2*)&C[(size_t)m * N + n] = v;
                }
            }
        }
    }
}

// ---------------------------------------------------------------------------
// Recurrence: per-token sequential softmax/steering chain in (L,E) space.
// 1 warp = 4 tokens. Lane t: b = t&7 (expert), lgrp = t>>3; lane owns
// slots (l = lgrp + 4i, b) for i=0..7  <=>  flat n = lane + 32*i.
// ---------------------------------------------------------------------------
__global__ __launch_bounds__(256) void recurrence_kernel(const float* __restrict__ br,
                                                         const float* __restrict__ ls) {
    __shared__ float Ms_sh[LAY * 72];     // row skew 72 -> conflict-free reads
    __shared__ float gate_sh[8][4][8];
    const int tid = threadIdx.x;
    const int w = tid >> 5, lane = tid & 31;
    const int b = lane & 7, lgrp = lane >> 3;
    const int tok0 = (blockIdx.x * 8 + w) * 4;

    float acc[4][8];
    #pragma unroll
    for (int t = 0; t < 4; t++) {
        const float* bp = g_base + (size_t)(tok0 + t) * N1;
        #pragma unroll
        for (int i = 0; i < 8; i++)
            acc[t][i] = bp[lane + 32 * i] + br[lane + 32 * i];
    }

    for (int j = 0; j < LAY; j++) {
        __syncthreads();
        {   // stage Ms[j] (2048 floats) into skewed shared
            const float4* src = (const float4*)(g_Ms + j * (LAY * NE * NE));
            #pragma unroll
            for (int p = 0; p < 2; p++) {
                int s4 = tid + p * 256;
                float4 v = src[s4];
                int l = s4 >> 4, r = (s4 & 15) << 2;
                *(float4*)&Ms_sh[l * 72 + r] = v;
            }
        }
        __syncthreads();

        const int ogrp = j & 3, ij = j >> 2;
        const float sj = ls[j];
        #pragma unroll
        for (int t = 0; t < 4; t++) {
            float v = acc[t][ij];
            float m = v;
            m = fmaxf(m, __shfl_xor_sync(0xffffffffu, m, 1));
            m = fmaxf(m, __shfl_xor_sync(0xffffffffu, m, 2));
            m = fmaxf(m, __shfl_xor_sync(0xffffffffu, m, 4));
            float e = __expf(v - m);
            float ssum = e;
            ssum += __shfl_xor_sync(0xffffffffu, ssum, 1);
            ssum += __shfl_xor_sync(0xffffffffu, ssum, 2);
            ssum += __shfl_xor_sync(0xffffffffu, ssum, 4);
            float gate = e / ssum;
            if (lgrp == ogrp) {
                gate_sh[w][t][b] = gate;
                g_gates[(size_t)(tok0 + t) * N1 + j * NE + b] = __float2bfloat16(gate * sj);
            }
        }
        __syncwarp();

        float ga[4][8];
        #pragma unroll
        for (int t = 0; t < 4; t++) {
            float4 g0 = *(float4*)&gate_sh[w][t][0];
            float4 g1 = *(float4*)&gate_sh[w][t][4];
            ga[t][0] = g0.x; ga[t][1] = g0.y; ga[t][2] = g0.z; ga[t][3] = g0.w;
            ga[t][4] = g1.x; ga[t][5] = g1.y; ga[t][6] = g1.z; ga[t][7] = g1.w;
        }
        #pragma unroll
        for (int i = 0; i < 8; i++) {
            int l = lgrp + 4 * i;
            if (l > j) {
                const float* mrow = &Ms_sh[l * 72 + b];
                #pragma unroll
                for (int a = 0; a < 8; a++) {
                    float ms = mrow[a * 8];
                    acc[0][i] = fmaf(ms, ga[0][a], acc[0][i]);
                    acc[1][i] = fmaf(ms, ga[1][a], acc[1][i]);
                    acc[2][i] = fmaf(ms, ga[2][a], acc[2][i]);
                    acc[3][i] = fmaf(ms, ga[3][a], acc[3][i]);
                }
            }
        }
        __syncwarp();
    }
}

// ---------------------------------------------------------------------------
// Final LayerNorm over F=1280 (one block per token, 320 threads x float4)
// ---------------------------------------------------------------------------
__global__ __launch_bounds__(320) void ln_kernel(const float* __restrict__ gamma,
                                                 const float* __restrict__ beta,
                                                 float* __restrict__ out) {
    __shared__ float red[2][10];
    const int tok = blockIdx.x, tid = threadIdx.x;
    float4 v = ((const float4*)(g_h + (size_t)tok * FD))[tid];
    float s = v.x + v.y + v.z + v.w;
    float q = v.x * v.x + v.y * v.y + v.z * v.z + v.w * v.w;
    #pragma unroll
    for (int d = 16; d > 0; d >>= 1) {
        s += __shfl_xor_sync(0xffffffffu, s, d);
        q += __shfl_xor_sync(0xffffffffu, q, d);
    }
    if ((tid & 31) == 0) { red[0][tid >> 5] = s; red[1][tid >> 5] = q; }
    __syncthreads();
    s = 0.f; q = 0.f;
    #pragma unroll
    for (int i = 0; i < 10; i++) { s += red[0][i]; q += red[1][i]; }
    const float inv = 1.f / (float)FD;
    float mu = s * inv;
    float var = q * inv - mu * mu;
    float rs = rsqrtf(var + LN_EPS);
    float4 g = ((const float4*)gamma)[tid];
    float4 bb = ((const float4*)beta)[tid];
    float4 o;
    o.x = (v.x - mu) * rs * g.x + bb.x;
    o.y = (v.y - mu) * rs * g.y + bb.y;
    o.z = (v.z - mu) * rs * g.z + bb.z;
    o.w = (v.w - mu) * rs * g.w + bb.w;
    ((float4*)out)[(size_t)tok * (FD / 4) + tid] = o;
}

// ---------------------------------------------------------------------------
// kernel_launch
// ---------------------------------------------------------------------------
extern "C" void kernel_launch(void* const* d_in, const int* in_sizes, int n_in,
                              void* d_out, int out_size) {
    const float* x     = (const float*)d_in[0];   // [16,1500,1280]
    const float* sv    = (const float*)d_in[1];   // [32,8,1280]
    const float* wr    = (const float*)d_in[2];   // [32,1280,8]
    const float* br    = (const float*)d_in[3];   // [32,8]
    const float* ls    = (const float*)d_in[4];   // [32]
    const float* gamma = (const float*)d_in[5];   // [1280]
    const float* beta  = (const float*)d_in[6];   // [1280]
    float* out = (float*)d_out;

    // x -> bf16 (7.68M float4s)
    convert_x_kernel<<<30000, 256>>>(x);
    // weight repack to bf16 (both operand layouts)
    prep_w_kernel<<<1280, 256>>>(wr, sv);
    // cross-layer steering->router matrices (with s_j folded in)
    prep_ms_kernel<<<dim3(LAY, LAY), 64>>>(sv, wr, ls);
    // GEMM1: base logits  [24000,256]
    gemm_k<1><<<dim3(N1 / GBN, (MTOK + GBM - 1) / GBM), 256>>>(nullptr);
    // sequential per-token recurrence -> scaled gates (bf16)
    recurrence_kernel<<<MTOK / 32, 256>>>(br, ls);
    // GEMM2 + epilogue: h = x + gates @ sv   [24000,1280]
    gemm_k<2><<<dim3(FD / GBN, (MTOK + GBM - 1) / GBM), 256>>>(x);
    // final LayerNorm
    ln_kernel<<<MTOK, 320>>>(gamma, beta, out);
}

// round 4
// speedup vs baseline: 1.0658x; 1.0658x over previous
#include <cuda_runtime.h>
#include <cuda_bf16.h>
#include <cstdint>

// Problem constants (fixed shapes)
#define MTOK   24000      // B*T = 16*1500
#define FD     1280       // d_model
#define LAY    32         // layers
#define NE     8          // experts
#define N1     256        // LAY*NE
#define LN_EPS 1e-5f

// ---------------------------------------------------------------------------
// Scratch (static __device__ arrays -- allocation-free per harness rules)
// ---------------------------------------------------------------------------
__device__ __nv_bfloat16 g_Wt[N1 * FD];                  // router_w as [n][f] bf16
__device__ __nv_bfloat16 g_svT[FD * N1];                 // steering as [f][n] bf16
__device__ float         g_Ms[LAY * LAY * NE * NE];      // s_j * sv_j @ Wr_l  [j][l][a][b]
__device__ float         g_base[(size_t)MTOK * N1];      // x @ Wr            24.6 MB
__device__ __nv_bfloat16 g_gates[(size_t)MTOK * N1];     // s_j*gate_j bf16   12.3 MB
__device__ float         g_h[(size_t)MTOK * FD];         // x + adj          123 MB

// ---------------------------------------------------------------------------
// small asm helpers
// ---------------------------------------------------------------------------
__device__ __forceinline__ uint32_t smem_u32(const void* p) {
    return (uint32_t)__cvta_generic_to_shared(p);
}
__device__ __forceinline__ void cp_async16(void* smem, const void* gmem) {
    asm volatile("cp.async.cg.shared.global [%0], [%1], 16;\n"
                 :: "r"(smem_u32(smem)), "l"(gmem));
}
__device__ __forceinline__ void cp_commit() {
    asm volatile("cp.async.commit_group;\n" ::);
}
__device__ __forceinline__ void cp_wait0() {
    asm volatile("cp.async.wait_group 0;\n" ::);
}
__device__ __forceinline__ void ldsm_x4(uint32_t* r, uint32_t a) {
    asm volatile("ldmatrix.sync.aligned.m8n8.x4.shared.b16 {%0,%1,%2,%3}, [%4];\n"
                 : "=r"(r[0]), "=r"(r[1]), "=r"(r[2]), "=r"(r[3]) : "r"(a));
}
__device__ __forceinline__ void mma_bf16(float* c, const uint32_t* a, uint32_t b0, uint32_t b1) {
    asm volatile("mma.sync.aligned.m16n8k16.row.col.f32.bf16.bf16.f32 "
                 "{%0,%1,%2,%3}, {%4,%5,%6,%7}, {%8,%9}, {%0,%1,%2,%3};\n"
                 : "+f"(c[0]), "+f"(c[1]), "+f"(c[2]), "+f"(c[3])
                 : "r"(a[0]), "r"(a[1]), "r"(a[2]), "r"(a[3]), "r"(b0), "r"(b1));
}

// ---------------------------------------------------------------------------
// Prep kernels
// ---------------------------------------------------------------------------
__global__ __launch_bounds__(256) void prep_w_kernel(const float* __restrict__ wr,
                                                     const float* __restrict__ sv) {
    int idx = blockIdx.x * 256 + threadIdx.x;         // 327,680 exactly
    int n = idx / FD, f = idx % FD;
    int l = n >> 3, e = n & 7;
    g_Wt[idx]                 = __float2bfloat16(wr[((size_t)l * FD + f) * NE + e]);
    g_svT[(size_t)f * N1 + n] = __float2bfloat16(sv[(size_t)n * FD + f]);
}

// Ms[j][l][a][b] = s_j * sum_f sv[j,a,f] * wr[l,f,b]
__global__ __launch_bounds__(64) void prep_ms_kernel(const float* __restrict__ sv,
                                                     const float* __restrict__ wr,
                                                     const float* __restrict__ ls) {
    int j = blockIdx.x, l = blockIdx.y;
    int b = threadIdx.x & 7, a = threadIdx.x >> 3;
    const float* svp = sv + (size_t)(j * NE + a) * FD;
    const float* wrp = wr + (size_t)l * FD * NE + b;
    float s = 0.f;
    #pragma unroll 4
    for (int f = 0; f < FD; f++) s = fmaf(svp[f], wrp[f * NE], s);
    g_Ms[((j * LAY + l) * NE + a) * NE + b] = s * ls[j];
}

// ---------------------------------------------------------------------------
// GEMM1: base[M,256] = x[M,1280](fp32, converted in-kernel) @ Wt[256,1280]^T
// Tile 64(M) x 256(N = full) x 32(K).  8 warps = 2(m) x 4(n); warp tile 32x64.
// A: LDG fp32 -> cvt bf16 -> STS, register-staged one tile ahead (x read ONCE).
//    As rows padded to 40 halves (80B stride; bank step 20 -> conflict-free).
// B: cp.async bf16, double buffered, XOR chunk swizzle on 64B rows:
//    phys_chunk = c ^ ((row>>1)&3)  -> conflict-free ldmatrix phases.
// Static smem: 10,240 + 32,768 = 43,008 B  (< 48 KB, no attribute needed).
// ---------------------------------------------------------------------------
#define G1_BM 64
#define G1_BK 32
#define G1_KT (FD / G1_BK)     // 40

__global__ __launch_bounds__(256) void gemm1_kernel(const float* __restrict__ X) {
    __shared__ __nv_bfloat16 As[2][G1_BM][40];
    __shared__ __nv_bfloat16 Bs[2][N1 * G1_BK];

    const int tid = threadIdx.x, lane = tid & 31, wrp = tid >> 5;
    const int wm = wrp & 1, wn = wrp >> 1;            // 2 x 4
    const int m0 = blockIdx.x * G1_BM;

    const int ar = tid >> 3;            // 0..31 (two rows: ar, ar+32)
    const int ac = tid & 7;             // float4 index within 32-float row

    float acc[2][8][4];
    #pragma unroll
    for (int mt = 0; mt < 2; mt++)
        #pragma unroll
        for (int nt = 0; nt < 8; nt++)
            #pragma unroll
            for (int q = 0; q < 4; q++) acc[mt][nt][q] = 0.f;

    float4 areg[2];

    auto ldg_A = [&](int kt) {
        #pragma unroll
        for (int p = 0; p < 2; p++)
            areg[p] = *(const float4*)&X[(size_t)(m0 + ar + p * 32) * FD + kt * G1_BK + ac * 4];
    };
    auto sts_A = [&](int buf) {
        #pragma unroll
        for (int p = 0; p < 2; p++) {
            __nv_bfloat162 h0 = __floats2bfloat162_rn(areg[p].x, areg[p].y);
            __nv_bfloat162 h1 = __floats2bfloat162_rn(areg[p].z, areg[p].w);
            uint2 v = make_uint2(*(uint32_t*)&h0, *(uint32_t*)&h1);
            *(uint2*)&As[buf][ar + p * 32][ac * 4] = v;
        }
    };
    auto cpa_B = [&](int buf, int kt) {
        #pragma unroll
        for (int q = 0; q < 4; q++) {
            int idx = q * 256 + tid;                  // 1024 chunks of 16B
            int r = idx >> 2, ch = idx & 3;
            int pc = ch ^ ((r >> 1) & 3);             // XOR swizzle
            cp_async16(&Bs[buf][r * G1_BK + pc * 8],
                       &g_Wt[(size_t)r * FD + kt * G1_BK + ch * 8]);
        }
    };

    // prologue
    ldg_A(0);
    sts_A(0);
    cpa_B(0, 0);
    cp_commit();

    for (int kt = 0; kt < G1_KT; kt++) {
        const int buf = kt & 1, nb = buf ^ 1;
        cp_wait0();
        __syncthreads();
        if (kt + 1 < G1_KT) {
            cpa_B(nb, kt + 1);
            cp_commit();
            ldg_A(kt + 1);
        }
        #pragma unroll
        for (int ks = 0; ks < 2; ks++) {
            uint32_t af[2][4], bq[4][4];
            #pragma unroll
            for (int mt = 0; mt < 2; mt++)
                ldsm_x4(af[mt], smem_u32(&As[buf][wm * 32 + mt * 16 + (lane & 15)]
                                            [ks * 16 + (lane >> 4) * 8]));
            #pragma unroll
            for (int np = 0; np < 4; np++) {
                int rr = wn * 64 + np * 16 + (lane & 15);
                int lc = ks * 2 + (lane >> 4);
                int pc = lc ^ ((rr >> 1) & 3);
                ldsm_x4(bq[np], smem_u32(&Bs[buf][rr * G1_BK + pc * 8]));
            }
            #pragma unroll
            for (int mt = 0; mt < 2; mt++)
                #pragma unroll
                for (int np = 0; np < 4; np++) {
                    mma_bf16(acc[mt][2 * np],     af[mt], bq[np][0], bq[np][2]);
                    mma_bf16(acc[mt][2 * np + 1], af[mt], bq[np][1], bq[np][3]);
                }
        }
        if (kt + 1 < G1_KT) sts_A(nb);
    }

    // epilogue: store base (M multiple of 64 exactly, no guards)
    const int gid = lane >> 2, qid = lane & 3;
    #pragma unroll
    for (int mt = 0; mt < 2; mt++) {
        #pragma unroll
        for (int nt = 0; nt < 8; nt++) {
            int n = wn * 64 + nt * 8 + qid * 2;
            #pragma unroll
            for (int h = 0; h < 2; h++) {
                int m = m0 + wm * 32 + mt * 16 + gid + h * 8;
                *(float2*)&g_base[(size_t)m * N1 + n] =
                    make_float2(acc[mt][nt][h * 2], acc[mt][nt][h * 2 + 1]);
            }
        }
    }
}

// ---------------------------------------------------------------------------
// GEMM2: h[M,1280] = x + gates[M,256] @ svT[1280,256]^T
// Tile 128 x 128 x 32, KT=8, double-buffered cp.async both operands.
// 8 warps = 4(m) x 2(n); warp tile 32x64. Rows padded to 40 halves (80B).
// Static smem: 2*(128+128)*40*2 = 40,960 B.
// ---------------------------------------------------------------------------
#define G2_BM 128
#define G2_BN 128
#define G2_BK 32
#define G2_KT (N1 / G2_BK)     // 8

__global__ __launch_bounds__(256) void gemm2_kernel(const float* __restrict__ X) {
    __shared__ __nv_bfloat16 As[2][G2_BM][40];
    __shared__ __nv_bfloat16 Bs[2][G2_BN][40];

    const int tid = threadIdx.x, lane = tid & 31, wrp = tid >> 5;
    const int wm = wrp & 3, wn = wrp >> 2;            // 4 x 2
    const int m0 = blockIdx.y * G2_BM, n0 = blockIdx.x * G2_BN;

    float acc[2][8][4];
    #pragma unroll
    for (int mt = 0; mt < 2; mt++)
        #pragma unroll
        for (int nt = 0; nt < 8; nt++)
            #pragma unroll
            for (int q = 0; q < 4; q++) acc[mt][nt][q] = 0.f;

    auto cpa_AB = [&](int buf, int kt) {
        #pragma unroll
        for (int q = 0; q < 2; q++) {
            int idx = q * 256 + tid;                  // 512 chunks each operand
            int r = idx >> 2, ch = idx & 3;
            int m = m0 + r; if (m >= MTOK) m = 0;     // clamp (discard at store)
            cp_async16(&As[buf][r][ch * 8], &g_gates[(size_t)m * N1 + kt * G2_BK + ch * 8]);
            cp_async16(&Bs[buf][r][ch * 8], &g_svT[(size_t)(n0 + r) * N1 + kt * G2_BK + ch * 8]);
        }
    };

    cpa_AB(0, 0);
    cp_commit();

    for (int kt = 0; kt < G2_KT; kt++) {
        const int buf = kt & 1, nb = buf ^ 1;
        cp_wait0();
        __syncthreads();
        if (kt + 1 < G2_KT) {
            cpa_AB(nb, kt + 1);
            cp_commit();
        }
        #pragma unroll
        for (int ks = 0; ks < 2; ks++) {
            uint32_t af[2][4], bq[4][4];
            #pragma unroll
            for (int mt = 0; mt < 2; mt++)
                ldsm_x4(af[mt], smem_u32(&As[buf][wm * 32 + mt * 16 + (lane & 15)]
                                            [ks * 16 + (lane >> 4) * 8]));
            #pragma unroll
            for (int np = 0; np < 4; np++)
                ldsm_x4(bq[np], smem_u32(&Bs[buf][wn * 64 + np * 16 + (lane & 15)]
                                            [ks * 16 + (lane >> 4) * 8]));
            #pragma unroll
            for (int mt = 0; mt < 2; mt++)
                #pragma unroll
                for (int np = 0; np < 4; np++) {
                    mma_bf16(acc[mt][2 * np],     af[mt], bq[np][0], bq[np][2]);
                    mma_bf16(acc[mt][2 * np + 1], af[mt], bq[np][1], bq[np][3]);
                }
        }
    }

    // epilogue: h = x + adj
    const int gid = lane >> 2, qid = lane & 3;
    #pragma unroll
    for (int mt = 0; mt < 2; mt++) {
        #pragma unroll
        for (int nt = 0; nt < 8; nt++) {
            int n = n0 + wn * 64 + nt * 8 + qid * 2;
            #pragma unroll
            for (int h = 0; h < 2; h++) {
                int m = m0 + wm * 32 + mt * 16 + gid + h * 8;
                if (m < MTOK) {
                    float2 xv = *(const float2*)&X[(size_t)m * FD + n];
                    *(float2*)&g_h[(size_t)m * FD + n] =
                        make_float2(acc[mt][nt][h * 2] + xv.x, acc[mt][nt][h * 2 + 1] + xv.y);
                }
            }
        }
    }
}

// ---------------------------------------------------------------------------
// Recurrence: per-token sequential softmax/steering chain in (L,E) space.
// 1 warp = 4 tokens. Lane t: b = t&7 (expert), lgrp = t>>3; lane owns
// slots (l = lgrp + 4i, b) for i=0..7  <=>  flat n = lane + 32*i.
// ---------------------------------------------------------------------------
__global__ __launch_bounds__(256) void recurrence_kernel(const float* __restrict__ br,
                                                         const float* __restrict__ ls) {
    __shared__ float Ms_sh[LAY * 72];     // row skew 72 -> conflict-free reads
    __shared__ float gate_sh[8][4][8];
    const int tid = threadIdx.x;
    const int w = tid >> 5, lane = tid & 31;
    const int b = lane & 7, lgrp = lane >> 3;
    const int tok0 = (blockIdx.x * 8 + w) * 4;

    float acc[4][8];
    #pragma unroll
    for (int t = 0; t < 4; t++) {
        const float* bp = g_base + (size_t)(tok0 + t) * N1;
        #pragma unroll
        for (int i = 0; i < 8; i++)
            acc[t][i] = bp[lane + 32 * i] + br[lane + 32 * i];
    }

    for (int j = 0; j < LAY; j++) {
        __syncthreads();
        {   // stage Ms[j] (2048 floats) into skewed shared
            const float4* src = (const float4*)(g_Ms + j * (LAY * NE * NE));
            #pragma unroll
            for (int p = 0; p < 2; p++) {
                int s4 = tid + p * 256;
                float4 v = src[s4];
                int l = s4 >> 4, r = (s4 & 15) << 2;
                *(float4*)&Ms_sh[l * 72 + r] = v;
            }
        }
        __syncthreads();

        const int ogrp = j & 3, ij = j >> 2;
        const float sj = ls[j];
        #pragma unroll
        for (int t = 0; t < 4; t++) {
            float v = acc[t][ij];
            float m = v;
            m = fmaxf(m, __shfl_xor_sync(0xffffffffu, m, 1));
            m = fmaxf(m, __shfl_xor_sync(0xffffffffu, m, 2));
            m = fmaxf(m, __shfl_xor_sync(0xffffffffu, m, 4));
            float e = __expf(v - m);
            float ssum = e;
            ssum += __shfl_xor_sync(0xffffffffu, ssum, 1);
            ssum += __shfl_xor_sync(0xffffffffu, ssum, 2);
            ssum += __shfl_xor_sync(0xffffffffu, ssum, 4);
            float gate = e / ssum;
            if (lgrp == ogrp) {
                gate_sh[w][t][b] = gate;
                g_gates[(size_t)(tok0 + t) * N1 + j * NE + b] = __float2bfloat16(gate * sj);
            }
        }
        __syncwarp();

        float ga[4][8];
        #pragma unroll
        for (int t = 0; t < 4; t++) {
            float4 g0 = *(float4*)&gate_sh[w][t][0];
            float4 g1 = *(float4*)&gate_sh[w][t][4];
            ga[t][0] = g0.x; ga[t][1] = g0.y; ga[t][2] = g0.z; ga[t][3] = g0.w;
            ga[t][4] = g1.x; ga[t][5] = g1.y; ga[t][6] = g1.z; ga[t][7] = g1.w;
        }
        #pragma unroll
        for (int i = 0; i < 8; i++) {
            int l = lgrp + 4 * i;
            if (l > j) {
                const float* mrow = &Ms_sh[l * 72 + b];
                #pragma unroll
                for (int a = 0; a < 8; a++) {
                    float ms = mrow[a * 8];
                    acc[0][i] = fmaf(ms, ga[0][a], acc[0][i]);
                    acc[1][i] = fmaf(ms, ga[1][a], acc[1][i]);
                    acc[2][i] = fmaf(ms, ga[2][a], acc[2][i]);
                    acc[3][i] = fmaf(ms, ga[3][a], acc[3][i]);
                }
            }
        }
        __syncwarp();
    }
}

// ---------------------------------------------------------------------------
// Final LayerNorm over F=1280 (one block per token, 320 threads x float4)
// ---------------------------------------------------------------------------
__global__ __launch_bounds__(320) void ln_kernel(const float* __restrict__ gamma,
                                                 const float* __restrict__ beta,
                                                 float* __restrict__ out) {
    __shared__ float red[2][10];
    const int tok = blockIdx.x, tid = threadIdx.x;
    float4 v = ((const float4*)(g_h + (size_t)tok * FD))[tid];
    float s = v.x + v.y + v.z + v.w;
    float q = v.x * v.x + v.y * v.y + v.z * v.z + v.w * v.w;
    #pragma unroll
    for (int d = 16; d > 0; d >>= 1) {
        s += __shfl_xor_sync(0xffffffffu, s, d);
        q += __shfl_xor_sync(0xffffffffu, q, d);
    }
    if ((tid & 31) == 0) { red[0][tid >> 5] = s; red[1][tid >> 5] = q; }
    __syncthreads();
    s = 0.f; q = 0.f;
    #pragma unroll
    for (int i = 0; i < 10; i++) { s += red[0][i]; q += red[1][i]; }
    const float inv = 1.f / (float)FD;
    float mu = s * inv;
    float var = q * inv - mu * mu;
    float rs = rsqrtf(var + LN_EPS);
    float4 g = ((const float4*)gamma)[tid];
    float4 bb = ((const float4*)beta)[tid];
    float4 o;
    o.x = (v.x - mu) * rs * g.x + bb.x;
    o.y = (v.y - mu) * rs * g.y + bb.y;
    o.z = (v.z - mu) * rs * g.z + bb.z;
    o.w = (v.w - mu) * rs * g.w + bb.w;
    ((float4*)out)[(size_t)tok * (FD / 4) + tid] = o;
}

// ---------------------------------------------------------------------------
// kernel_launch  (launches ONLY -- no attributes, no memcpy, no allocation)
// ---------------------------------------------------------------------------
extern "C" void kernel_launch(void* const* d_in, const int* in_sizes, int n_in,
                              void* d_out, int out_size) {
    const float* x     = (const float*)d_in[0];   // [16,1500,1280]
    const float* sv    = (const float*)d_in[1];   // [32,8,1280]
    const float* wr    = (const float*)d_in[2];   // [32,1280,8]
    const float* br    = (const float*)d_in[3];   // [32,8]
    const float* ls    = (const float*)d_in[4];   // [32]
    const float* gamma = (const float*)d_in[5];   // [1280]
    const float* beta  = (const float*)d_in[6];   // [1280]
    float* out = (float*)d_out;

    // weight repack to bf16 (both operand layouts)
    prep_w_kernel<<<1280, 256>>>(wr, sv);
    // cross-layer steering->router matrices (with s_j folded in)
    prep_ms_kernel<<<dim3(LAY, LAY), 64>>>(sv, wr, ls);
    // GEMM1: base logits [24000,256] (x converted in-kernel, read once)
    gemm1_kernel<<<MTOK / G1_BM, 256>>>(x);
    // sequential per-token recurrence -> scaled gates (bf16)
    recurrence_kernel<<<MTOK / 32, 256>>>(br, ls);
    // GEMM2 + epilogue: h = x + gates @ sv   [24000,1280]
    gemm2_kernel<<<dim3(FD / G2_BN, (MTOK + G2_BM - 1) / G2_BM), 256>>>(x);
    // final LayerNorm
    ln_kernel<<<MTOK, 320>>>(gamma, beta, out);
}

// round 5
// speedup vs baseline: 1.1431x; 1.0726x over previous
#include <cuda_runtime.h>
#include <cuda_bf16.h>
#include <cstdint>

// Problem constants (fixed shapes)
#define MTOK   24000      // B*T = 16*1500
#define FD     1280       // d_model
#define LAY    32         // layers
#define NE     8          // experts
#define N1     256        // LAY*NE
#define LN_EPS 1e-5f

// ---------------------------------------------------------------------------
// Scratch (static __device__ arrays -- allocation-free per harness rules)
// ---------------------------------------------------------------------------
__device__ __nv_bfloat16 g_Wt[N1 * FD];                  // router_w as [n][f] bf16
__device__ __nv_bfloat16 g_svT[FD * N1];                 // steering as [f][n] bf16
__device__ __nv_bfloat16 g_Msb[LAY * LAY * NE * NE * 2]; // s_j*sv_j@Wr_l bf16 DUP: [j][l][b][a*2]
__device__ float         g_base[(size_t)MTOK * N1];      // x @ Wr            24.6 MB
__device__ __nv_bfloat16 g_gates[(size_t)MTOK * N1];     // s_j*gate_j bf16   12.3 MB
__device__ float         g_h[(size_t)MTOK * FD];         // x + adj          123 MB

// ---------------------------------------------------------------------------
// small asm helpers
// ---------------------------------------------------------------------------
__device__ __forceinline__ uint32_t smem_u32(const void* p) {
    return (uint32_t)__cvta_generic_to_shared(p);
}
__device__ __forceinline__ void cp_async16(void* smem, const void* gmem) {
    asm volatile("cp.async.cg.shared.global [%0], [%1], 16;\n"
                 :: "r"(smem_u32(smem)), "l"(gmem));
}
__device__ __forceinline__ void cp_commit() {
    asm volatile("cp.async.commit_group;\n" ::);
}
__device__ __forceinline__ void cp_wait0() {
    asm volatile("cp.async.wait_group 0;\n" ::);
}
__device__ __forceinline__ void ldsm_x4(uint32_t* r, uint32_t a) {
    asm volatile("ldmatrix.sync.aligned.m8n8.x4.shared.b16 {%0,%1,%2,%3}, [%4];\n"
                 : "=r"(r[0]), "=r"(r[1]), "=r"(r[2]), "=r"(r[3]) : "r"(a));
}
__device__ __forceinline__ void mma_bf16(float* c, const uint32_t* a, uint32_t b0, uint32_t b1) {
    asm volatile("mma.sync.aligned.m16n8k16.row.col.f32.bf16.bf16.f32 "
                 "{%0,%1,%2,%3}, {%4,%5,%6,%7}, {%8,%9}, {%0,%1,%2,%3};\n"
                 : "+f"(c[0]), "+f"(c[1]), "+f"(c[2]), "+f"(c[3])
                 : "r"(a[0]), "r"(a[1]), "r"(a[2]), "r"(a[3]), "r"(b0), "r"(b1));
}

// ---------------------------------------------------------------------------
// Prep kernels
// ---------------------------------------------------------------------------
__global__ __launch_bounds__(256) void prep_w_kernel(const float* __restrict__ wr,
                                                     const float* __restrict__ sv) {
    int idx = blockIdx.x * 256 + threadIdx.x;         // 327,680 exactly
    int n = idx / FD, f = idx % FD;
    int l = n >> 3, e = n & 7;
    g_Wt[idx]                 = __float2bfloat16(wr[((size_t)l * FD + f) * NE + e]);
    g_svT[(size_t)f * N1 + n] = __float2bfloat16(sv[(size_t)n * FD + f]);
}

// Ms[j][l][a][b] = s_j * sum_f sv[j,a,f] * wr[l,f,b]  -> stored bf16 duplicated
// layout [j][l][b][a*2 + {0,1}]  (each value twice -> ready-made HFMA2 operand)
__global__ __launch_bounds__(64) void prep_ms_kernel(const float* __restrict__ sv,
                                                     const float* __restrict__ wr,
                                                     const float* __restrict__ ls) {
    int j = blockIdx.x, l = blockIdx.y;
    int b = threadIdx.x & 7, a = threadIdx.x >> 3;
    const float* svp = sv + (size_t)(j * NE + a) * FD;
    const float* wrp = wr + (size_t)l * FD * NE + b;
    float s = 0.f;
    #pragma unroll 4
    for (int f = 0; f < FD; f++) s = fmaf(svp[f], wrp[f * NE], s);
    float v = s * ls[j];
    __nv_bfloat162 d = __float2bfloat162_rn(v);       // (v, v)
    ((__nv_bfloat162*)g_Msb)[(((j * LAY + l) * NE + b) * NE + a)] = d;
}

// ---------------------------------------------------------------------------
// GEMM1: base[M,256] = x[M,1280](fp32, converted in-kernel) @ Wt[256,1280]^T
// Tile 64(M) x 256(N = full) x 32(K).  8 warps = 2(m) x 4(n); warp tile 32x64.
// ---------------------------------------------------------------------------
#define G1_BM 64
#define G1_BK 32
#define G1_KT (FD / G1_BK)     // 40

__global__ __launch_bounds__(256) void gemm1_kernel(const float* __restrict__ X) {
    __shared__ __nv_bfloat16 As[2][G1_BM][40];
    __shared__ __nv_bfloat16 Bs[2][N1 * G1_BK];

    const int tid = threadIdx.x, lane = tid & 31, wrp = tid >> 5;
    const int wm = wrp & 1, wn = wrp >> 1;            // 2 x 4
    const int m0 = blockIdx.x * G1_BM;

    const int ar = tid >> 3;            // 0..31 (two rows: ar, ar+32)
    const int ac = tid & 7;             // float4 index within 32-float row

    float acc[2][8][4];
    #pragma unroll
    for (int mt = 0; mt < 2; mt++)
        #pragma unroll
        for (int nt = 0; nt < 8; nt++)
            #pragma unroll
            for (int q = 0; q < 4; q++) acc[mt][nt][q] = 0.f;

    float4 areg[2];

    auto ldg_A = [&](int kt) {
        #pragma unroll
        for (int p = 0; p < 2; p++)
            areg[p] = *(const float4*)&X[(size_t)(m0 + ar + p * 32) * FD + kt * G1_BK + ac * 4];
    };
    auto sts_A = [&](int buf) {
        #pragma unroll
        for (int p = 0; p < 2; p++) {
            __nv_bfloat162 h0 = __floats2bfloat162_rn(areg[p].x, areg[p].y);
            __nv_bfloat162 h1 = __floats2bfloat162_rn(areg[p].z, areg[p].w);
            uint2 v = make_uint2(*(uint32_t*)&h0, *(uint32_t*)&h1);
            *(uint2*)&As[buf][ar + p * 32][ac * 4] = v;
        }
    };
    auto cpa_B = [&](int buf, int kt) {
        #pragma unroll
        for (int q = 0; q < 4; q++) {
            int idx = q * 256 + tid;                  // 1024 chunks of 16B
            int r = idx >> 2, ch = idx & 3;
            int pc = ch ^ ((r >> 1) & 3);             // XOR swizzle
            cp_async16(&Bs[buf][r * G1_BK + pc * 8],
                       &g_Wt[(size_t)r * FD + kt * G1_BK + ch * 8]);
        }
    };

    ldg_A(0);
    sts_A(0);
    cpa_B(0, 0);
    cp_commit();

    for (int kt = 0; kt < G1_KT; kt++) {
        const int buf = kt & 1, nb = buf ^ 1;
        cp_wait0();
        __syncthreads();
        if (kt + 1 < G1_KT) {
            cpa_B(nb, kt + 1);
            cp_commit();
            ldg_A(kt + 1);
        }
        #pragma unroll
        for (int ks = 0; ks < 2; ks++) {
            uint32_t af[2][4], bq[4][4];
            #pragma unroll
            for (int mt = 0; mt < 2; mt++)
                ldsm_x4(af[mt], smem_u32(&As[buf][wm * 32 + mt * 16 + (lane & 15)]
                                            [ks * 16 + (lane >> 4) * 8]));
            #pragma unroll
            for (int np = 0; np < 4; np++) {
                int rr = wn * 64 + np * 16 + (lane & 15);
                int lc = ks * 2 + (lane >> 4);
                int pc = lc ^ ((rr >> 1) & 3);
                ldsm_x4(bq[np], smem_u32(&Bs[buf][rr * G1_BK + pc * 8]));
            }
            #pragma unroll
            for (int mt = 0; mt < 2; mt++)
                #pragma unroll
                for (int np = 0; np < 4; np++) {
                    mma_bf16(acc[mt][2 * np],     af[mt], bq[np][0], bq[np][2]);
                    mma_bf16(acc[mt][2 * np + 1], af[mt], bq[np][1], bq[np][3]);
                }
        }
        if (kt + 1 < G1_KT) sts_A(nb);
    }

    const int gid = lane >> 2, qid = lane & 3;
    #pragma unroll
    for (int mt = 0; mt < 2; mt++) {
        #pragma unroll
        for (int nt = 0; nt < 8; nt++) {
            int n = wn * 64 + nt * 8 + qid * 2;
            #pragma unroll
            for (int h = 0; h < 2; h++) {
                int m = m0 + wm * 32 + mt * 16 + gid + h * 8;
                *(float2*)&g_base[(size_t)m * N1 + n] =
                    make_float2(acc[mt][nt][h * 2], acc[mt][nt][h * 2 + 1]);
            }
        }
    }
}

// ---------------------------------------------------------------------------
// GEMM2: h[M,1280] = x + gates[M,256] @ svT[1280,256]^T
// Tile 128 x 128 x 32, KT=8, double-buffered cp.async both operands.
// ---------------------------------------------------------------------------
#define G2_BM 128
#define G2_BN 128
#define G2_BK 32
#define G2_KT (N1 / G2_BK)     // 8

__global__ __launch_bounds__(256) void gemm2_kernel(const float* __restrict__ X) {
    __shared__ __nv_bfloat16 As[2][G2_BM][40];
    __shared__ __nv_bfloat16 Bs[2][G2_BN][40];

    const int tid = threadIdx.x, lane = tid & 31, wrp = tid >> 5;
    const int wm = wrp & 3, wn = wrp >> 2;            // 4 x 2
    const int m0 = blockIdx.y * G2_BM, n0 = blockIdx.x * G2_BN;

    float acc[2][8][4];
    #pragma unroll
    for (int mt = 0; mt < 2; mt++)
        #pragma unroll
        for (int nt = 0; nt < 8; nt++)
            #pragma unroll
            for (int q = 0; q < 4; q++) acc[mt][nt][q] = 0.f;

    auto cpa_AB = [&](int buf, int kt) {
        #pragma unroll
        for (int q = 0; q < 2; q++) {
            int idx = q * 256 + tid;                  // 512 chunks each operand
            int r = idx >> 2, ch = idx & 3;
            int m = m0 + r; if (m >= MTOK) m = 0;     // clamp (discard at store)
            cp_async16(&As[buf][r][ch * 8], &g_gates[(size_t)m * N1 + kt * G2_BK + ch * 8]);
            cp_async16(&Bs[buf][r][ch * 8], &g_svT[(size_t)(n0 + r) * N1 + kt * G2_BK + ch * 8]);
        }
    };

    cpa_AB(0, 0);
    cp_commit();

    for (int kt = 0; kt < G2_KT; kt++) {
        const int buf = kt & 1, nb = buf ^ 1;
        cp_wait0();
        __syncthreads();
        if (kt + 1 < G2_KT) {
            cpa_AB(nb, kt + 1);
            cp_commit();
        }
        #pragma unroll
        for (int ks = 0; ks < 2; ks++) {
            uint32_t af[2][4], bq[4][4];
            #pragma unroll
            for (int mt = 0; mt < 2; mt++)
                ldsm_x4(af[mt], smem_u32(&As[buf][wm * 32 + mt * 16 + (lane & 15)]
                                            [ks * 16 + (lane >> 4) * 8]));
            #pragma unroll
            for (int np = 0; np < 4; np++)
                ldsm_x4(bq[np], smem_u32(&Bs[buf][wn * 64 + np * 16 + (lane & 15)]
                                            [ks * 16 + (lane >> 4) * 8]));
            #pragma unroll
            for (int mt = 0; mt < 2; mt++)
                #pragma unroll
                for (int np = 0; np < 4; np++) {
                    mma_bf16(acc[mt][2 * np],     af[mt], bq[np][0], bq[np][2]);
                    mma_bf16(acc[mt][2 * np + 1], af[mt], bq[np][1], bq[np][3]);
                }
        }
    }

    const int gid = lane >> 2, qid = lane & 3;
    #pragma unroll
    for (int mt = 0; mt < 2; mt++) {
        #pragma unroll
        for (int nt = 0; nt < 8; nt++) {
            int n = n0 + wn * 64 + nt * 8 + qid * 2;
            #pragma unroll
            for (int h = 0; h < 2; h++) {
                int m = m0 + wm * 32 + mt * 16 + gid + h * 8;
                if (m < MTOK) {
                    float2 xv = *(const float2*)&X[(size_t)m * FD + n];
                    *(float2*)&g_h[(size_t)m * FD + n] =
                        make_float2(acc[mt][nt][h * 2] + xv.x, acc[mt][nt][h * 2 + 1] + xv.y);
                }
            }
        }
    }
}

// ---------------------------------------------------------------------------
// Recurrence v2: fp32 base logits (immutable) + bf16x2 steering correction.
// 1 warp = 4 tokens (2 HFMA2 pairs). Lane = lgrp*8 + b owns slots
// (l = lgrp + 4i, b), i = 0..7.
// Ms staged 4 layers per sync round, bf16 DUP layout with bank skew:
//   byte(l, b, a-pair h) = l*272 + b*32 + (b>>2)*16 + h*16   (conflict-free)
// ---------------------------------------------------------------------------
#define RW 4                   // warps per block
#define RJW 4                  // layers staged per round
#define MS_LB 272              // bytes per l-row in staged layout
#define MS_JB (LAY * MS_LB)    // 8704 bytes per staged layer

__global__ __launch_bounds__(128) void recurrence_kernel(const float* __restrict__ br,
                                                         const float* __restrict__ ls) {
    __shared__ __align__(16) char  Ms_sh[RJW * MS_JB];  // 34,816 B
    __shared__ float gate_sh[RW][4][8];

    const int tid = threadIdx.x;
    const int w = tid >> 5, lane = tid & 31;
    const int b = lane & 7, lgrp = lane >> 3;
    const int tok0 = (blockIdx.x * RW + w) * 4;

    // immutable fp32 base logits (x@Wr + bias)
    float base[4][8];
    #pragma unroll
    for (int t = 0; t < 4; t++) {
        const float* bp = g_base + (size_t)(tok0 + t) * N1;
        #pragma unroll
        for (int i = 0; i < 8; i++)
            base[t][i] = bp[lane + 32 * i] + br[lane + 32 * i];
    }
    // bf16x2 correction accumulators: pair p packs tokens (2p, 2p+1)
    __nv_bfloat162 corr[2][8];
    #pragma unroll
    for (int p = 0; p < 2; p++)
        #pragma unroll
        for (int i = 0; i < 8; i++) corr[p][i] = __float2bfloat162_rn(0.f);

    for (int jr = 0; jr < LAY / RJW; jr++) {
        __syncthreads();
        // stage Ms for layers j0..j0+3 (2048 x 16B chunks, 128 threads)
        {
            const char* src = (const char*)g_Msb + (size_t)(jr * RJW) * (LAY * NE * NE * 4);
            #pragma unroll
            for (int q = 0; q < 16; q++) {
                int c = q * 128 + tid;                // 0..2047
                int jj = c >> 9, r = c & 511;
                int l = r >> 4, rr = r & 15;
                int bb = rr >> 1, hh = rr & 1;
                int dst = jj * MS_JB + l * MS_LB + bb * 32 + (bb >> 2) * 16 + hh * 16;
                cp_async16(Ms_sh + dst, src + (size_t)c * 16);
            }
        }
        cp_commit();
        cp_wait0();
        __syncthreads();

        #pragma unroll
        for (int jj = 0; jj < RJW; jj++) {
            const int j = jr * RJW + jj;
            const int ogrp = j & 3, ij = j >> 2;
            const float sj = ls[j];

            // softmax over expert octets (only octet ogrp is layer j)
            #pragma unroll
            for (int t = 0; t < 4; t++) {
                float cf = (t & 1) ? __bfloat162float(__high2bfloat16(corr[t >> 1][ij]))
                                   : __bfloat162float(__low2bfloat16(corr[t >> 1][ij]));
                float v = base[t][ij] + cf;
                float m = v;
                m = fmaxf(m, __shfl_xor_sync(0xffffffffu, m, 1));
                m = fmaxf(m, __shfl_xor_sync(0xffffffffu, m, 2));
                m = fmaxf(m, __shfl_xor_sync(0xffffffffu, m, 4));
                float e = __expf(v - m);
                float ssum = e;
                ssum += __shfl_xor_sync(0xffffffffu, ssum, 1);
                ssum += __shfl_xor_sync(0xffffffffu, ssum, 2);
                ssum += __shfl_xor_sync(0xffffffffu, ssum, 4);
                float gate = __fdividef(e, ssum);
                if (lgrp == ogrp) {
                    gate_sh[w][t][b] = gate;
                    g_gates[(size_t)(tok0 + t) * N1 + j * NE + b] = __float2bfloat16(gate * sj);
                }
            }
            __syncwarp();

            // pack gates: ga[p][a] = (gate[2p][a], gate[2p+1][a]) bf16x2
            __nv_bfloat162 ga[2][8];
            #pragma unroll
            for (int p = 0; p < 2; p++) {
                #pragma unroll
                for (int a4 = 0; a4 < 2; a4++) {
                    float4 u = *(float4*)&gate_sh[w][2 * p][a4 * 4];
                    float4 v = *(float4*)&gate_sh[w][2 * p + 1][a4 * 4];
                    ga[p][a4 * 4 + 0] = __floats2bfloat162_rn(u.x, v.x);
                    ga[p][a4 * 4 + 1] = __floats2bfloat162_rn(u.y, v.y);
                    ga[p][a4 * 4 + 2] = __floats2bfloat162_rn(u.z, v.z);
                    ga[p][a4 * 4 + 3] = __floats2bfloat162_rn(u.w, v.w);
                }
            }
            __syncwarp();

            // corr[l>j] += gate @ Ms[j]
            const char* msj = Ms_sh + jj * MS_JB;
            #pragma unroll
            for (int i = 0; i < 8; i++) {
                int l = lgrp + 4 * i;
                if (l > j) {
                    const uint4* mp = (const uint4*)(msj + l * MS_LB + b * 32 + (b >> 2) * 16);
                    uint4 m0 = mp[0], m1 = mp[1];
                    const __nv_bfloat162* ms = (const __nv_bfloat162*)&m0;
                    #pragma unroll
                    for (int a = 0; a < 4; a++) {
                        corr[0][i] = __hfma2(ms[a], ga[0][a], corr[0][i]);
                        corr[1][i] = __hfma2(ms[a], ga[1][a], corr[1][i]);
                    }
                    const __nv_bfloat162* ms2 = (const __nv_bfloat162*)&m1;
                    #pragma unroll
                    for (int a = 0; a < 4; a++) {
                        corr[0][i] = __hfma2(ms2[a], ga[0][a + 4], corr[0][i]);
                        corr[1][i] = __hfma2(ms2[a], ga[1][a + 4], corr[1][i]);
                    }
                }
            }
        }
    }
}

// ---------------------------------------------------------------------------
// Final LayerNorm over F=1280 (one block per token, 320 threads x float4)
// ---------------------------------------------------------------------------
__global__ __launch_bounds__(320) void ln_kernel(const float* __restrict__ gamma,
                                                 const float* __restrict__ beta,
                                                 float* __restrict__ out) {
    __shared__ float red[2][10];
    const int tok = blockIdx.x, tid = threadIdx.x;
    float4 v = ((const float4*)(g_h + (size_t)tok * FD))[tid];
    float s = v.x + v.y + v.z + v.w;
    float q = v.x * v.x + v.y * v.y + v.z * v.z + v.w * v.w;
    #pragma unroll
    for (int d = 16; d > 0; d >>= 1) {
        s += __shfl_xor_sync(0xffffffffu, s, d);
        q += __shfl_xor_sync(0xffffffffu, q, d);
    }
    if ((tid & 31) == 0) { red[0][tid >> 5] = s; red[1][tid >> 5] = q; }
    __syncthreads();
    s = 0.f; q = 0.f;
    #pragma unroll
    for (int i = 0; i < 10; i++) { s += red[0][i]; q += red[1][i]; }
    const float inv = 1.f / (float)FD;
    float mu = s * inv;
    float var = q * inv - mu * mu;
    float rs = rsqrtf(var + LN_EPS);
    float4 g = ((const float4*)gamma)[tid];
    float4 bb = ((const float4*)beta)[tid];
    float4 o;
    o.x = (v.x - mu) * rs * g.x + bb.x;
    o.y = (v.y - mu) * rs * g.y + bb.y;
    o.z = (v.z - mu) * rs * g.z + bb.z;
    o.w = (v.w - mu) * rs * g.w + bb.w;
    ((float4*)out)[(size_t)tok * (FD / 4) + tid] = o;
}

// ---------------------------------------------------------------------------
// kernel_launch  (launches ONLY -- no attributes, no memcpy, no allocation)
// ---------------------------------------------------------------------------
extern "C" void kernel_launch(void* const* d_in, const int* in_sizes, int n_in,
                              void* d_out, int out_size) {
    const float* x     = (const float*)d_in[0];   // [16,1500,1280]
    const float* sv    = (const float*)d_in[1];   // [32,8,1280]
    const float* wr    = (const float*)d_in[2];   // [32,1280,8]
    const float* br    = (const float*)d_in[3];   // [32,8]
    const float* ls    = (const float*)d_in[4];   // [32]
    const float* gamma = (const float*)d_in[5];   // [1280]
    const float* beta  = (const float*)d_in[6];   // [1280]
    float* out = (float*)d_out;

    // weight repack to bf16 (both operand layouts)
    prep_w_kernel<<<1280, 256>>>(wr, sv);
    // cross-layer steering->router matrices (bf16 dup, s_j folded)
    prep_ms_kernel<<<dim3(LAY, LAY), 64>>>(sv, wr, ls);
    // GEMM1: base logits [24000,256] (x converted in-kernel, read once)
    gemm1_kernel<<<MTOK / G1_BM, 256>>>(x);
    // sequential per-token recurrence -> scaled gates (bf16)
    recurrence_kernel<<<MTOK / (RW * 4), 128>>>(br, ls);
    // GEMM2 + epilogue: h = x + gates @ sv   [24000,1280]
    gemm2_kernel<<<dim3(FD / G2_BN, (MTOK + G2_BM - 1) / G2_BM), 256>>>(x);
    // final LayerNorm
    ln_kernel<<<MTOK, 320>>>(gamma, beta, out);
}

// round 6
// speedup vs baseline: 1.4186x; 1.2410x over previous
#include <cuda_runtime.h>
#include <cuda_bf16.h>
#include <cstdint>

// Problem constants (fixed shapes)
#define MTOK   24000      // B*T = 16*1500
#define FD     1280       // d_model
#define LAY    32         // layers
#define NE     8          // experts
#define N1     256        // LAY*NE
#define LN_EPS 1e-5f

// ---------------------------------------------------------------------------
// Scratch (static __device__ arrays -- allocation-free per harness rules)
// ---------------------------------------------------------------------------
__device__ __nv_bfloat16 g_Wt[N1 * FD];                  // router_w as [n][f] bf16
__device__ __nv_bfloat16 g_svT[FD * N1];                 // steering as [f][n] bf16
__device__ __nv_bfloat16 g_Msb[LAY * NE * N1];           // raw sv_j@Wr bf16: [j][a][l*8+b]
__device__ float         g_base[(size_t)MTOK * N1];      // x @ Wr            24.6 MB
__device__ __nv_bfloat16 g_gates[(size_t)MTOK * N1];     // s_j*gate_j bf16   12.3 MB
__device__ float         g_h[(size_t)MTOK * FD];         // x + adj          123 MB

// ---------------------------------------------------------------------------
// small asm helpers
// ---------------------------------------------------------------------------
__device__ __forceinline__ uint32_t smem_u32(const void* p) {
    return (uint32_t)__cvta_generic_to_shared(p);
}
__device__ __forceinline__ void cp_async16(void* smem, const void* gmem) {
    asm volatile("cp.async.cg.shared.global [%0], [%1], 16;\n"
                 :: "r"(smem_u32(smem)), "l"(gmem));
}
__device__ __forceinline__ void cp_commit() {
    asm volatile("cp.async.commit_group;\n" ::);
}
__device__ __forceinline__ void cp_wait0() {
    asm volatile("cp.async.wait_group 0;\n" ::);
}
__device__ __forceinline__ void ldsm_x4(uint32_t* r, uint32_t a) {
    asm volatile("ldmatrix.sync.aligned.m8n8.x4.shared.b16 {%0,%1,%2,%3}, [%4];\n"
                 : "=r"(r[0]), "=r"(r[1]), "=r"(r[2]), "=r"(r[3]) : "r"(a));
}
__device__ __forceinline__ void ldsm_x4_t(uint32_t* r, uint32_t a) {
    asm volatile("ldmatrix.sync.aligned.m8n8.x4.trans.shared.b16 {%0,%1,%2,%3}, [%4];\n"
                 : "=r"(r[0]), "=r"(r[1]), "=r"(r[2]), "=r"(r[3]) : "r"(a));
}
__device__ __forceinline__ void mma_bf16(float* c, const uint32_t* a, uint32_t b0, uint32_t b1) {
    asm volatile("mma.sync.aligned.m16n8k16.row.col.f32.bf16.bf16.f32 "
                 "{%0,%1,%2,%3}, {%4,%5,%6,%7}, {%8,%9}, {%0,%1,%2,%3};\n"
                 : "+f"(c[0]), "+f"(c[1]), "+f"(c[2]), "+f"(c[3])
                 : "r"(a[0]), "r"(a[1]), "r"(a[2]), "r"(a[3]), "r"(b0), "r"(b1));
}
__device__ __forceinline__ void mma_bf16_k8(float* c, uint32_t a0, uint32_t a1, uint32_t b0) {
    asm volatile("mma.sync.aligned.m16n8k8.row.col.f32.bf16.bf16.f32 "
                 "{%0,%1,%2,%3}, {%4,%5}, {%6}, {%0,%1,%2,%3};\n"
                 : "+f"(c[0]), "+f"(c[1]), "+f"(c[2]), "+f"(c[3])
                 : "r"(a0), "r"(a1), "r"(b0));
}

// ---------------------------------------------------------------------------
// Prep kernels
// ---------------------------------------------------------------------------
__global__ __launch_bounds__(256) void prep_w_kernel(const float* __restrict__ wr,
                                                     const float* __restrict__ sv) {
    int idx = blockIdx.x * 256 + threadIdx.x;         // 327,680 exactly
    int n = idx / FD, f = idx % FD;
    int l = n >> 3, e = n & 7;
    g_Wt[idx]                 = __float2bfloat16(wr[((size_t)l * FD + f) * NE + e]);
    g_svT[(size_t)f * N1 + n] = __float2bfloat16(sv[(size_t)n * FD + f]);
}

// Ms[j][a][l*8+b] = sum_f sv[j,a,f] * wr[l,f,b]   (raw, NO ls scale -- folded
// into the gates inside the recurrence kernel)
__global__ __launch_bounds__(64) void prep_ms_kernel(const float* __restrict__ sv,
                                                     const float* __restrict__ wr) {
    int j = blockIdx.x, l = blockIdx.y;
    int b = threadIdx.x & 7, a = threadIdx.x >> 3;
    const float* svp = sv + (size_t)(j * NE + a) * FD;
    const float* wrp = wr + (size_t)l * FD * NE + b;
    float s = 0.f;
    #pragma unroll 4
    for (int f = 0; f < FD; f++) s = fmaf(svp[f], wrp[f * NE], s);
    g_Msb[((size_t)(j * NE + a)) * N1 + l * NE + b] = __float2bfloat16(s);
}

// ---------------------------------------------------------------------------
// GEMM1: base[M,256] = x[M,1280](fp32, converted in-kernel) @ Wt[256,1280]^T
// Tile 64(M) x 256(N = full) x 32(K).  8 warps = 2(m) x 4(n); warp tile 32x64.
// ---------------------------------------------------------------------------
#define G1_BM 64
#define G1_BK 32
#define G1_KT (FD / G1_BK)     // 40

__global__ __launch_bounds__(256) void gemm1_kernel(const float* __restrict__ X) {
    __shared__ __nv_bfloat16 As[2][G1_BM][40];
    __shared__ __nv_bfloat16 Bs[2][N1 * G1_BK];

    const int tid = threadIdx.x, lane = tid & 31, wrp = tid >> 5;
    const int wm = wrp & 1, wn = wrp >> 1;            // 2 x 4
    const int m0 = blockIdx.x * G1_BM;

    const int ar = tid >> 3;            // 0..31 (two rows: ar, ar+32)
    const int ac = tid & 7;             // float4 index within 32-float row

    float acc[2][8][4];
    #pragma unroll
    for (int mt = 0; mt < 2; mt++)
        #pragma unroll
        for (int nt = 0; nt < 8; nt++)
            #pragma unroll
            for (int q = 0; q < 4; q++) acc[mt][nt][q] = 0.f;

    float4 areg[2];

    auto ldg_A = [&](int kt) {
        #pragma unroll
        for (int p = 0; p < 2; p++)
            areg[p] = *(const float4*)&X[(size_t)(m0 + ar + p * 32) * FD + kt * G1_BK + ac * 4];
    };
    auto sts_A = [&](int buf) {
        #pragma unroll
        for (int p = 0; p < 2; p++) {
            __nv_bfloat162 h0 = __floats2bfloat162_rn(areg[p].x, areg[p].y);
            __nv_bfloat162 h1 = __floats2bfloat162_rn(areg[p].z, areg[p].w);
            uint2 v = make_uint2(*(uint32_t*)&h0, *(uint32_t*)&h1);
            *(uint2*)&As[buf][ar + p * 32][ac * 4] = v;
        }
    };
    auto cpa_B = [&](int buf, int kt) {
        #pragma unroll
        for (int q = 0; q < 4; q++) {
            int idx = q * 256 + tid;                  // 1024 chunks of 16B
            int r = idx >> 2, ch = idx & 3;
            int pc = ch ^ ((r >> 1) & 3);             // XOR swizzle
            cp_async16(&Bs[buf][r * G1_BK + pc * 8],
                       &g_Wt[(size_t)r * FD + kt * G1_BK + ch * 8]);
        }
    };

    ldg_A(0);
    sts_A(0);
    cpa_B(0, 0);
    cp_commit();

    for (int kt = 0; kt < G1_KT; kt++) {
        const int buf = kt & 1, nb = buf ^ 1;
        cp_wait0();
        __syncthreads();
        if (kt + 1 < G1_KT) {
            cpa_B(nb, kt + 1);
            cp_commit();
            ldg_A(kt + 1);
        }
        #pragma unroll
        for (int ks = 0; ks < 2; ks++) {
            uint32_t af[2][4], bq[4][4];
            #pragma unroll
            for (int mt = 0; mt < 2; mt++)
                ldsm_x4(af[mt], smem_u32(&As[buf][wm * 32 + mt * 16 + (lane & 15)]
                                            [ks * 16 + (lane >> 4) * 8]));
            #pragma unroll
            for (int np = 0; np < 4; np++) {
                int rr = wn * 64 + np * 16 + (lane & 15);
                int lc = ks * 2 + (lane >> 4);
                int pc = lc ^ ((rr >> 1) & 3);
                ldsm_x4(bq[np], smem_u32(&Bs[buf][rr * G1_BK + pc * 8]));
            }
            #pragma unroll
            for (int mt = 0; mt < 2; mt++)
                #pragma unroll
                for (int np = 0; np < 4; np++) {
                    mma_bf16(acc[mt][2 * np],     af[mt], bq[np][0], bq[np][2]);
                    mma_bf16(acc[mt][2 * np + 1], af[mt], bq[np][1], bq[np][3]);
                }
        }
        if (kt + 1 < G1_KT) sts_A(nb);
    }

    const int gid = lane >> 2, qid = lane & 3;
    #pragma unroll
    for (int mt = 0; mt < 2; mt++) {
        #pragma unroll
        for (int nt = 0; nt < 8; nt++) {
            int n = wn * 64 + nt * 8 + qid * 2;
            #pragma unroll
            for (int h = 0; h < 2; h++) {
                int m = m0 + wm * 32 + mt * 16 + gid + h * 8;
                *(float2*)&g_base[(size_t)m * N1 + n] =
                    make_float2(acc[mt][nt][h * 2], acc[mt][nt][h * 2 + 1]);
            }
        }
    }
}

// ---------------------------------------------------------------------------
// GEMM2: h[M,1280] = x + gates[M,256] @ svT[1280,256]^T
// Tile 128 x 128 x 32, KT=8, double-buffered cp.async both operands.
// ---------------------------------------------------------------------------
#define G2_BM 128
#define G2_BN 128
#define G2_BK 32
#define G2_KT (N1 / G2_BK)     // 8

__global__ __launch_bounds__(256) void gemm2_kernel(const float* __restrict__ X) {
    __shared__ __nv_bfloat16 As[2][G2_BM][40];
    __shared__ __nv_bfloat16 Bs[2][G2_BN][40];

    const int tid = threadIdx.x, lane = tid & 31, wrp = tid >> 5;
    const int wm = wrp & 3, wn = wrp >> 2;            // 4 x 2
    const int m0 = blockIdx.y * G2_BM, n0 = blockIdx.x * G2_BN;

    float acc[2][8][4];
    #pragma unroll
    for (int mt = 0; mt < 2; mt++)
        #pragma unroll
        for (int nt = 0; nt < 8; nt++)
            #pragma unroll
            for (int q = 0; q < 4; q++) acc[mt][nt][q] = 0.f;

    auto cpa_AB = [&](int buf, int kt) {
        #pragma unroll
        for (int q = 0; q < 2; q++) {
            int idx = q * 256 + tid;                  // 512 chunks each operand
            int r = idx >> 2, ch = idx & 3;
            int m = m0 + r; if (m >= MTOK) m = 0;     // clamp (discard at store)
            cp_async16(&As[buf][r][ch * 8], &g_gates[(size_t)m * N1 + kt * G2_BK + ch * 8]);
            cp_async16(&Bs[buf][r][ch * 8], &g_svT[(size_t)(n0 + r) * N1 + kt * G2_BK + ch * 8]);
        }
    };

    cpa_AB(0, 0);
    cp_commit();

    for (int kt = 0; kt < G2_KT; kt++) {
        const int buf = kt & 1, nb = buf ^ 1;
        cp_wait0();
        __syncthreads();
        if (kt + 1 < G2_KT) {
            cpa_AB(nb, kt + 1);
            cp_commit();
        }
        #pragma unroll
        for (int ks = 0; ks < 2; ks++) {
            uint32_t af[2][4], bq[4][4];
            #pragma unroll
            for (int mt = 0; mt < 2; mt++)
                ldsm_x4(af[mt], smem_u32(&As[buf][wm * 32 + mt * 16 + (lane & 15)]
                                            [ks * 16 + (lane >> 4) * 8]));
            #pragma unroll
            for (int np = 0; np < 4; np++)
                ldsm_x4(bq[np], smem_u32(&Bs[buf][wn * 64 + np * 16 + (lane & 15)]
                                            [ks * 16 + (lane >> 4) * 8]));
            #pragma unroll
            for (int mt = 0; mt < 2; mt++)
                #pragma unroll
                for (int np = 0; np < 4; np++) {
                    mma_bf16(acc[mt][2 * np],     af[mt], bq[np][0], bq[np][2]);
                    mma_bf16(acc[mt][2 * np + 1], af[mt], bq[np][1], bq[np][3]);
                }
        }
    }

    const int gid = lane >> 2, qid = lane & 3;
    #pragma unroll
    for (int mt = 0; mt < 2; mt++) {
        #pragma unroll
        for (int nt = 0; nt < 8; nt++) {
            int n = n0 + wn * 64 + nt * 8 + qid * 2;
            #pragma unroll
            for (int h = 0; h < 2; h++) {
                int m = m0 + wm * 32 + mt * 16 + gid + h * 8;
                if (m < MTOK) {
                    float2 xv = *(const float2*)&X[(size_t)m * FD + n];
                    *(float2*)&g_h[(size_t)m * FD + n] =
                        make_float2(acc[mt][nt][h * 2] + xv.x, acc[mt][nt][h * 2 + 1] + xv.y);
                }
            }
        }
    }
}

// ---------------------------------------------------------------------------
// Recurrence v3 (tensor-core): each warp owns 16 tokens x all 256 logit slots
// as fp32 m16n8 C-fragments (32 octets x 4 regs = 128 regs).
// Per layer j: in-register softmax on octet j (C-fragment layout == A-fragment
// layout for m16n8k8!), cvt gates (s_j folded) to bf16x2 -> A operand,
// then acc += gates @ Ms[j] over ALL 32 octets (8 ldsm.x4.trans + 32 mma).
// Octets l <= j get polluted -- harmless, they are never read again.
// Ms staged 8 layers/round, rows skewed 528B -> conflict-free ldsm phases.
// ---------------------------------------------------------------------------
#define RB_W 4                       // warps per block
#define RB_TOK (RB_W * 16)           // 64 tokens per block
#define RJ 8                         // layers staged per round
#define MS_ROW 528                   // bytes per k-row (512 + 16 skew)
#define MS_JSZ (NE * MS_ROW)         // 4224 B per layer

__global__ __launch_bounds__(128) void recurrence_kernel(const float* __restrict__ br,
                                                         const float* __restrict__ ls) {
    __shared__ __align__(16) char Ms_sh[RJ * MS_JSZ];    // 33,792 B

    const int tid = threadIdx.x, w = tid >> 5, lane = tid & 31;
    const int gid = lane >> 2, qid = lane & 3;
    const int tokw = blockIdx.x * RB_TOK + w * 16;

    // fp32 logit state: 32 octets x 4 regs (C-fragment layout)
    float acc[LAY][4];
    #pragma unroll
    for (int nt = 0; nt < LAY; nt++) {
        float2 bias = *(const float2*)&br[nt * 8 + qid * 2];
        float2 v0 = *(const float2*)&g_base[(size_t)(tokw + gid) * N1 + nt * 8 + qid * 2];
        float2 v1 = *(const float2*)&g_base[(size_t)(tokw + gid + 8) * N1 + nt * 8 + qid * 2];
        acc[nt][0] = v0.x + bias.x; acc[nt][1] = v0.y + bias.y;
        acc[nt][2] = v1.x + bias.x; acc[nt][3] = v1.y + bias.y;
    }

    #pragma unroll
    for (int jr = 0; jr < LAY / RJ; jr++) {
        __syncthreads();
        // stage Ms for layers jr*RJ .. +7  (2048 x 16B chunks, 128 threads)
        {
            const char* src = (const char*)g_Msb + (size_t)(jr * RJ) * (NE * N1 * 2);
            #pragma unroll
            for (int q = 0; q < 16; q++) {
                int c = q * 128 + tid;                // 0..2047
                int jj = c >> 8;                      // 256 chunks per layer
                int r = c & 255;
                int k = r >> 5, oct = r & 31;
                cp_async16(Ms_sh + jj * MS_JSZ + k * MS_ROW + oct * 16,
                           src + (size_t)jj * (NE * N1 * 2) + (size_t)(k * N1 + oct * 8) * 2);
            }
        }
        cp_commit();
        cp_wait0();
        __syncthreads();

        #pragma unroll
        for (int jj = 0; jj < RJ; jj++) {
            const int j = jr * RJ + jj;

            // --- softmax on octet j (rows gid and gid+8), across qid lanes ---
            float m0 = fmaxf(acc[j][0], acc[j][1]);
            float m1 = fmaxf(acc[j][2], acc[j][3]);
            m0 = fmaxf(m0, __shfl_xor_sync(0xffffffffu, m0, 1));
            m0 = fmaxf(m0, __shfl_xor_sync(0xffffffffu, m0, 2));
            m1 = fmaxf(m1, __shfl_xor_sync(0xffffffffu, m1, 1));
            m1 = fmaxf(m1, __shfl_xor_sync(0xffffffffu, m1, 2));
            float e0 = __expf(acc[j][0] - m0), e1 = __expf(acc[j][1] - m0);
            float e2 = __expf(acc[j][2] - m1), e3 = __expf(acc[j][3] - m1);
            float s0 = e0 + e1, s1 = e2 + e3;
            s0 += __shfl_xor_sync(0xffffffffu, s0, 1);
            s0 += __shfl_xor_sync(0xffffffffu, s0, 2);
            s1 += __shfl_xor_sync(0xffffffffu, s1, 1);
            s1 += __shfl_xor_sync(0xffffffffu, s1, 2);
            const float sj = ls[j];
            float r0 = __fdividef(sj, s0), r1 = __fdividef(sj, s1);

            // scaled gates, bf16x2 == A-fragment regs for m16n8k8
            __nv_bfloat162 A0 = __floats2bfloat162_rn(e0 * r0, e1 * r0);
            __nv_bfloat162 A1 = __floats2bfloat162_rn(e2 * r1, e3 * r1);
            uint32_t a0 = *(uint32_t*)&A0, a1 = *(uint32_t*)&A1;

            // emit s_j*gate for GEMM2 (fragment-pattern stores)
            *(uint32_t*)&g_gates[(size_t)(tokw + gid) * N1 + j * 8 + qid * 2]     = a0;
            *(uint32_t*)&g_gates[(size_t)(tokw + gid + 8) * N1 + j * 8 + qid * 2] = a1;

            // --- acc += gates @ Ms[j] over all 32 octets ---
            const char* msj = Ms_sh + jj * MS_JSZ;
            #pragma unroll
            for (int g4 = 0; g4 < 8; g4++) {
                uint32_t b[4];
                ldsm_x4_t(b, smem_u32(msj + (lane & 7) * MS_ROW + (g4 * 4 + (lane >> 3)) * 16));
                #pragma unroll
                for (int q = 0; q < 4; q++)
                    mma_bf16_k8(acc[g4 * 4 + q], a0, a1, b[q]);
            }
        }
    }
}

// ---------------------------------------------------------------------------
// Final LayerNorm over F=1280 (one block per token, 320 threads x float4)
// ---------------------------------------------------------------------------
__global__ __launch_bounds__(320) void ln_kernel(const float* __restrict__ gamma,
                                                 const float* __restrict__ beta,
                                                 float* __restrict__ out) {
    __shared__ float red[2][10];
    const int tok = blockIdx.x, tid = threadIdx.x;
    float4 v = ((const float4*)(g_h + (size_t)tok * FD))[tid];
    float s = v.x + v.y + v.z + v.w;
    float q = v.x * v.x + v.y * v.y + v.z * v.z + v.w * v.w;
    #pragma unroll
    for (int d = 16; d > 0; d >>= 1) {
        s += __shfl_xor_sync(0xffffffffu, s, d);
        q += __shfl_xor_sync(0xffffffffu, q, d);
    }
    if ((tid & 31) == 0) { red[0][tid >> 5] = s; red[1][tid >> 5] = q; }
    __syncthreads();
    s = 0.f; q = 0.f;
    #pragma unroll
    for (int i = 0; i < 10; i++) { s += red[0][i]; q += red[1][i]; }
    const float inv = 1.f / (float)FD;
    float mu = s * inv;
    float var = q * inv - mu * mu;
    float rs = rsqrtf(var + LN_EPS);
    float4 g = ((const float4*)gamma)[tid];
    float4 bb = ((const float4*)beta)[tid];
    float4 o;
    o.x = (v.x - mu) * rs * g.x + bb.x;
    o.y = (v.y - mu) * rs * g.y + bb.y;
    o.z = (v.z - mu) * rs * g.z + bb.z;
    o.w = (v.w - mu) * rs * g.w + bb.w;
    ((float4*)out)[(size_t)tok * (FD / 4) + tid] = o;
}

// ---------------------------------------------------------------------------
// kernel_launch  (launches ONLY -- no attributes, no memcpy, no allocation)
// ---------------------------------------------------------------------------
extern "C" void kernel_launch(void* const* d_in, const int* in_sizes, int n_in,
                              void* d_out, int out_size) {
    const float* x     = (const float*)d_in[0];   // [16,1500,1280]
    const float* sv    = (const float*)d_in[1];   // [32,8,1280]
    const float* wr    = (const float*)d_in[2];   // [32,1280,8]
    const float* br    = (const float*)d_in[3];   // [32,8]
    const float* ls    = (const float*)d_in[4];   // [32]
    const float* gamma = (const float*)d_in[5];   // [1280]
    const float* beta  = (const float*)d_in[6];   // [1280]
    float* out = (float*)d_out;

    // weight repack to bf16 (both operand layouts)
    prep_w_kernel<<<1280, 256>>>(wr, sv);
    // cross-layer steering->router matrices (raw bf16, [j][a][l*8+b])
    prep_ms_kernel<<<dim3(LAY, LAY), 64>>>(sv, wr);
    // GEMM1: base logits [24000,256] (x converted in-kernel, read once)
    gemm1_kernel<<<MTOK / G1_BM, 256>>>(x);
    // tensor-core per-token recurrence -> scaled gates (bf16)
    recurrence_kernel<<<MTOK / RB_TOK, 128>>>(br, ls);
    // GEMM2 + epilogue: h = x + gates @ sv   [24000,1280]
    gemm2_kernel<<<dim3(FD / G2_BN, (MTOK + G2_BM - 1) / G2_BM), 256>>>(x);
    // final LayerNorm
    ln_kernel<<<MTOK, 320>>>(gamma, beta, out);
}